// round 16
// baseline (speedup 1.0000x reference)
#include <cuda_runtime.h>
#include <cuda_fp16.h>
#include <cstdint>

#define DIM      128
#define N_NODES  50000
#define N_EDGES  625000
#define TILE_M   64
#define NTILES   ((N_NODES + TILE_M - 1) / TILE_M)   // 782

#define INIT_BLOCKS  ((N_NODES * (DIM / 4) + 255) / 256)   // 6250
#define HIST_BLOCKS  ((N_EDGES / 4 + 255) / 256)           // 611

// SMEM geometry for final kernel: 64-row A tiles (hi only) + full 128-row B.
#define ASTRIDE   272
#define AB        (64 * ASTRIDE)                     // 17408
#define BB        (128 * ASTRIDE)                    // 34816
#define SM_A1H    0
#define SM_A2H    (AB)
#define SM_B1     (2 * AB)
#define SM_B2     (2 * AB + BB)
#define SM_TOTAL  (2 * AB + 2 * BB)                  // 104448 -> 2 CTAs/SM

// ---------------- scratch (device globals) ----------------------------------
__device__ __half g_aggH[(size_t)N_NODES * DIM];     // fp16 aggX
__device__ __half g_Xh[(size_t)N_NODES * DIM];       // fp16 copy of X
__device__ __half g_Wh[2][DIM * DIM];                // [(1+eps)lin_W, C=lin_W.msg_W]
__device__ float  g_c2[DIM];                         // lin_W . msg_b
__device__ int    g_ei_is_i64;
// CSR build
__device__ int    g_cnt[N_NODES];
__device__ int    g_off[N_NODES + 1];
__device__ int    g_cur[N_NODES];
__device__ int    g_sorted[N_EDGES];

// ---------------- helpers ----------------------------------------------------
__device__ __forceinline__ uint32_t smem_u32(const void* p) {
    uint32_t a;
    asm("{ .reg .u64 t; cvta.to.shared.u64 t, %1; cvt.u32.u64 %0, t; }" : "=r"(a) : "l"(p));
    return a;
}

#define LDSM_X4(r, addr)                                                        \
    asm volatile("ldmatrix.sync.aligned.m8n8.x4.shared.b16 {%0,%1,%2,%3}, [%4];"\
                 : "=r"((r)[0]), "=r"((r)[1]), "=r"((r)[2]), "=r"((r)[3])       \
                 : "r"(addr))
#define MMA_FP16(c, a, b0, b1)                                                  \
    asm volatile("mma.sync.aligned.m16n8k16.row.col.f32.f16.f16.f32 "           \
                 "{%0,%1,%2,%3}, {%4,%5,%6,%7}, {%8,%9}, {%0,%1,%2,%3};"        \
                 : "+f"((c)[0]), "+f"((c)[1]), "+f"((c)[2]), "+f"((c)[3])       \
                 : "r"((a)[0]), "r"((a)[1]), "r"((a)[2]), "r"((a)[3]),          \
                   "r"(b0), "r"(b1))

// vectorized 4-edge decode (src + dst)
__device__ __forceinline__ void edge_decode4(const void* ei, int e0,
                                             unsigned* s, unsigned* d) {
    if (g_ei_is_i64) {
        const longlong2* p = (const longlong2*)ei;
        longlong2 a = __ldg(p + e0 / 2), b = __ldg(p + e0 / 2 + 1);
        longlong2 c = __ldg(p + (N_EDGES + e0) / 2), e = __ldg(p + (N_EDGES + e0) / 2 + 1);
        s[0] = (unsigned)a.x; s[1] = (unsigned)a.y; s[2] = (unsigned)b.x; s[3] = (unsigned)b.y;
        d[0] = (unsigned)c.x; d[1] = (unsigned)c.y; d[2] = (unsigned)e.x; d[3] = (unsigned)e.y;
    } else {
        int4 a = __ldg((const int4*)ei + e0 / 4);
        int4 c = __ldg((const int4*)ei + (N_EDGES + e0) / 4);
        s[0] = (unsigned)a.x; s[1] = (unsigned)a.y; s[2] = (unsigned)a.z; s[3] = (unsigned)a.w;
        d[0] = (unsigned)c.x; d[1] = (unsigned)c.y; d[2] = (unsigned)c.z; d[3] = (unsigned)c.w;
    }
}

// ---------------- k1: detect dtype (block 0) + zero counters -----------------
__global__ void detect_zero_kernel(const unsigned* __restrict__ p32) {
    const int i = blockIdx.x * blockDim.x + threadIdx.x;
    if (i < N_NODES) g_cnt[i] = 0;
    if (blockIdx.x == 0) {
        __shared__ unsigned red[256];
        unsigned acc = 0;
        for (int k = threadIdx.x; k < 1024; k += 256) {
            acc |= p32[2 * k + 1];
            acc |= p32[2 * (N_EDGES / 2 + k) + 1];
        }
        red[threadIdx.x] = acc;
        __syncthreads();
        for (int s = 128; s > 0; s >>= 1) {
            if (threadIdx.x < s) red[threadIdx.x] |= red[threadIdx.x + s];
            __syncthreads();
        }
        if (threadIdx.x == 0) g_ei_is_i64 = (red[0] == 0) ? 1 : 0;
    }
}

// ---------------- k2: convert X/lin_W to fp16 (+hist, merged) ----------------
__global__ void init_hist_kernel(const float* __restrict__ lin_w,
                                 const float* __restrict__ X,
                                 const float* __restrict__ eps_ptr,
                                 const void* __restrict__ ei) {
    const int b = blockIdx.x;
    if (b < INIT_BLOCKS) {
        const int i = b * blockDim.x + threadIdx.x;
        if (i < DIM * DIM) {
            const float epsv = 1.0f + __ldg(eps_ptr);
            g_Wh[0][i] = __float2half(epsv * lin_w[i]);   // fold (1+eps) into B1
        }
        if (i < N_NODES * (DIM / 4)) {
            float4 v = __ldg((const float4*)X + i);
            __half2 h0 = __floats2half2_rn(v.x, v.y);
            __half2 h1 = __floats2half2_rn(v.z, v.w);
            uint2 u;
            u.x = *(uint32_t*)&h0;
            u.y = *(uint32_t*)&h1;
            ((uint2*)g_Xh)[i] = u;
        }
    } else {
        const int e0 = ((b - INIT_BLOCKS) * blockDim.x + threadIdx.x) * 4;
        if (e0 >= N_EDGES) return;
        unsigned s[4], d[4];
        edge_decode4(ei, e0, s, d);
        #pragma unroll
        for (int i = 0; i < 4; i++)
            if (e0 + i < N_EDGES && s[i] < N_NODES && d[i] < N_NODES)
                atomicAdd(&g_cnt[s[i]], 1);
    }
}

// ---------------- k3: prep C/c2 (blocks 0..15) + single-block scan (block 16)
// prep: C = lin_W . msg_W (fp32 acc -> fp16), c2 = lin_W . msg_b. 8 rows/block.
// scan: exclusive prefix over g_cnt by one 1024-thread block.
__global__ void __launch_bounds__(1024, 1)
prep_scan_kernel(const float* __restrict__ lin_w,
                 const float* __restrict__ msg_w,
                 const float* __restrict__ msg_b) {
    if (blockIdx.x < 16) {
        __shared__ float s[8][DIM];
        __shared__ float red[8][DIM];
        const int r = threadIdx.x >> 7;            // row within block, 0..7
        const int j = threadIdx.x & 127;
        const int row = blockIdx.x * 8 + r;
        s[r][j] = lin_w[(size_t)row * DIM + j];
        __syncthreads();
        float acc = 0.f;
        #pragma unroll 8
        for (int k = 0; k < DIM; k++)
            acc += s[r][k] * __ldg(msg_w + (size_t)k * DIM + j);
        g_Wh[1][(size_t)row * DIM + j] = __float2half(acc);
        red[r][j] = s[r][j] * __ldg(msg_b + j);
        __syncthreads();
        for (int st = 64; st > 0; st >>= 1) {
            if (j < st) red[r][j] += red[r][j + st];
            __syncthreads();
        }
        if (j == 0) g_c2[row] = red[r][0];
    } else {
        // single-block scan over g_cnt[0..N_NODES)
        __shared__ int sm[1024];
        const int t = threadIdx.x;
        const int per = (N_NODES + 1023) / 1024;   // 49
        const int base = t * per;
        const int lim = (base + per < N_NODES) ? base + per : N_NODES;
        int sum = 0;
        for (int i = base; i < lim; i++) sum += g_cnt[i];
        sm[t] = sum;
        __syncthreads();
        // Hillis-Steele inclusive scan
        #pragma unroll
        for (int off = 1; off < 1024; off <<= 1) {
            int x = (t >= off) ? sm[t - off] : 0;
            __syncthreads();
            sm[t] += x;
            __syncthreads();
        }
        int run = sm[t] - sum;                      // exclusive prefix
        for (int i = base; i < lim; i++) {
            int c = g_cnt[i];
            g_off[i] = run;
            g_cur[i] = run;
            run += c;
        }
        if (t == 1023) g_off[N_NODES] = run;        // total (tail threads empty)
    }
}

__global__ void reorder_kernel(const void* __restrict__ ei) {
    const int e0 = (blockIdx.x * blockDim.x + threadIdx.x) * 4;
    if (e0 >= N_EDGES) return;
    unsigned s[4], d[4];
    edge_decode4(ei, e0, s, d);
    #pragma unroll
    for (int i = 0; i < 4; i++)
        if (e0 + i < N_EDGES && s[i] < N_NODES && d[i] < N_NODES) {
            int pos = atomicAdd(&g_cur[s[i]], 1);
            g_sorted[pos] = (int)d[i];
        }
}

// ---------------- SpMM: aggH[n] = fp16( sum over CSR dst rows of fp16 X ) ----
__global__ void spmm_kernel() {
    const int node = blockIdx.x * (blockDim.x >> 5) + (threadIdx.x >> 5);
    if (node >= N_NODES) return;
    const int lane = threadIdx.x & 31;
    const int start = __ldg(&g_off[node]);
    const int end   = __ldg(&g_off[node + 1]);
    const uint2* Xh = (const uint2*)g_Xh;

    float4 a0 = make_float4(0.f, 0.f, 0.f, 0.f);
    float4 a1 = a0, a2 = a0, a3 = a0;
    int i = start;
    for (; i + 4 <= end; i += 4) {
        const int d0 = __ldg(&g_sorted[i + 0]);
        const int d1 = __ldg(&g_sorted[i + 1]);
        const int d2 = __ldg(&g_sorted[i + 2]);
        const int d3 = __ldg(&g_sorted[i + 3]);
        uint2 u0 = __ldg(Xh + (size_t)d0 * (DIM / 4) + lane);
        uint2 u1 = __ldg(Xh + (size_t)d1 * (DIM / 4) + lane);
        uint2 u2 = __ldg(Xh + (size_t)d2 * (DIM / 4) + lane);
        uint2 u3 = __ldg(Xh + (size_t)d3 * (DIM / 4) + lane);
        float2 p, q;
        p = __half22float2(*(__half2*)&u0.x); q = __half22float2(*(__half2*)&u0.y);
        a0.x += p.x; a0.y += p.y; a0.z += q.x; a0.w += q.y;
        p = __half22float2(*(__half2*)&u1.x); q = __half22float2(*(__half2*)&u1.y);
        a1.x += p.x; a1.y += p.y; a1.z += q.x; a1.w += q.y;
        p = __half22float2(*(__half2*)&u2.x); q = __half22float2(*(__half2*)&u2.y);
        a2.x += p.x; a2.y += p.y; a2.z += q.x; a2.w += q.y;
        p = __half22float2(*(__half2*)&u3.x); q = __half22float2(*(__half2*)&u3.y);
        a3.x += p.x; a3.y += p.y; a3.z += q.x; a3.w += q.y;
    }
    for (; i < end; i++) {
        const int d = __ldg(&g_sorted[i]);
        uint2 u = __ldg(Xh + (size_t)d * (DIM / 4) + lane);
        float2 p = __half22float2(*(__half2*)&u.x);
        float2 q = __half22float2(*(__half2*)&u.y);
        a0.x += p.x; a0.y += p.y; a0.z += q.x; a0.w += q.y;
    }
    a0.x += a1.x + a2.x + a3.x;
    a0.y += a1.y + a2.y + a3.y;
    a0.z += a1.z + a2.z + a3.z;
    a0.w += a1.w + a2.w + a3.w;
    __half2 h0 = __floats2half2_rn(a0.x, a0.y);
    __half2 h1 = __floats2half2_rn(a0.z, a0.w);
    uint2 u;
    u.x = *(uint32_t*)&h0;
    u.y = *(uint32_t*)&h1;
    ((uint2*)g_aggH)[(size_t)node * (DIM / 4) + lane] = u;
}

// ---------------- final: out = relu(Xh.[(1+eps)lin_W]^T + aggH.C^T + deg*c2 + lin_b)
// 64-row tiles, 256 threads (8 warps), 2 CTAs/SM. A1/A2 are pure fp16 copies.
__global__ void __launch_bounds__(256, 2)
final_kernel(const float* __restrict__ lin_b, float* __restrict__ out) {
    extern __shared__ char smem[];
    const uint32_t sb = smem_u32(smem);
    const int tid = threadIdx.x;
    const int w = tid >> 5, t = tid & 31;
    const int s = w >> 1, h = w & 1;
    const int g = t >> 2, tig = t & 3;
    const int base = blockIdx.x * TILE_M;

    // ---- fill: A1h = copy(Xh), A2h = copy(aggH), B1/B2 = copy ----
    {
        const int row = tid >> 2;                 // 0..63
        const int c0 = (tid & 3) * 32;
        const int grow = base + row;
        const bool v = (grow < N_NODES);
        uint4* a1d = (uint4*)(smem + SM_A1H + (uint32_t)row * ASTRIDE + (uint32_t)c0 * 2);
        uint4* a2d = (uint4*)(smem + SM_A2H + (uint32_t)row * ASTRIDE + (uint32_t)c0 * 2);
        if (v) {
            const uint4* a1s = (const uint4*)(g_Xh + (size_t)grow * DIM + c0);
            const uint4* a2s = (const uint4*)(g_aggH + (size_t)grow * DIM + c0);
            #pragma unroll
            for (int i = 0; i < 4; i++) { a1d[i] = __ldg(a1s + i); a2d[i] = __ldg(a2s + i); }
        } else {
            #pragma unroll
            for (int i = 0; i < 4; i++) {
                a1d[i] = make_uint4(0u, 0u, 0u, 0u);
                a2d[i] = make_uint4(0u, 0u, 0u, 0u);
            }
        }
        // B tiles: 128 rows; thread covers half a row (64 cols = 8 uint4)
        const int brow = tid >> 1;
        const int bc0 = (tid & 1) * 64;
        const uint4* b1s = (const uint4*)(&g_Wh[0][(size_t)brow * DIM + bc0]);
        const uint4* b2s = (const uint4*)(&g_Wh[1][(size_t)brow * DIM + bc0]);
        uint4* b1d = (uint4*)(smem + SM_B1 + (uint32_t)brow * ASTRIDE + (uint32_t)bc0 * 2);
        uint4* b2d = (uint4*)(smem + SM_B2 + (uint32_t)brow * ASTRIDE + (uint32_t)bc0 * 2);
        #pragma unroll
        for (int i = 0; i < 8; i++) { b1d[i] = __ldg(b1s + i); b2d[i] = __ldg(b2s + i); }
    }
    __syncthreads();

    float acc[8][4];
    #pragma unroll
    for (int j = 0; j < 8; j++)
        #pragma unroll
        for (int i = 0; i < 4; i++) acc[j][i] = 0.f;

    // ---- MMA: acc = A1h.B1 + A2h.B2 ----
    #pragma unroll 1
    for (int k = 0; k < 8; k++) {
        const uint32_t a_off = (uint32_t)(s * 16 + (t & 15)) * ASTRIDE
                             + (uint32_t)k * 32 + (uint32_t)(t >> 4) * 16;
        uint32_t a1[4], a2[4];
        LDSM_X4(a1, sb + SM_A1H + a_off);
        LDSM_X4(a2, sb + SM_A2H + a_off);
        #pragma unroll
        for (int jp = 0; jp < 4; jp++) {
            const uint32_t b_off =
                  (uint32_t)((h * 8 + jp * 2) * 8 + (t >> 4) * 8 + (t & 7)) * ASTRIDE
                + (uint32_t)k * 32 + (uint32_t)((t >> 3) & 1) * 16;
            uint32_t b1[4], b2[4];
            LDSM_X4(b1, sb + SM_B1 + b_off);
            LDSM_X4(b2, sb + SM_B2 + b_off);
            MMA_FP16(acc[jp * 2 + 0], a1, b1[0], b1[1]);
            MMA_FP16(acc[jp * 2 + 0], a2, b2[0], b2[1]);
            MMA_FP16(acc[jp * 2 + 1], a1, b1[2], b1[3]);
            MMA_FP16(acc[jp * 2 + 1], a2, b2[2], b2[3]);
        }
    }

    // ---- epilogue ----
    const int r0 = s * 16 + g, r1 = r0 + 8;
    const int gr0 = base + r0, gr1 = base + r1;
    const bool v0 = (gr0 < N_NODES), v1 = (gr1 < N_NODES);
    const float d0 = v0 ? (float)(__ldg(&g_off[gr0 + 1]) - __ldg(&g_off[gr0])) : 0.f;
    const float d1 = v1 ? (float)(__ldg(&g_off[gr1 + 1]) - __ldg(&g_off[gr1])) : 0.f;
    #pragma unroll
    for (int j = 0; j < 8; j++) {
        const int col = h * 64 + j * 8 + 2 * tig;
        float2 lb = __ldg((const float2*)(lin_b + col));
        float2 c2 = __ldg((const float2*)(g_c2 + col));
        if (v0) {
            float2 o;
            o.x = fmaxf(acc[j][0] + d0 * c2.x + lb.x, 0.f);
            o.y = fmaxf(acc[j][1] + d0 * c2.y + lb.y, 0.f);
            *(float2*)(out + (size_t)gr0 * DIM + col) = o;
        }
        if (v1) {
            float2 o;
            o.x = fmaxf(acc[j][2] + d1 * c2.x + lb.x, 0.f);
            o.y = fmaxf(acc[j][3] + d1 * c2.y + lb.y, 0.f);
            *(float2*)(out + (size_t)gr1 * DIM + col) = o;
        }
    }
}

// ---------------- launch ----------------------------------------------------
extern "C" void kernel_launch(void* const* d_in, const int* in_sizes, int n_in,
                              void* d_out, int out_size) {
    const float* X   = nullptr;
    const void*  ei  = nullptr;
    const float* eps = nullptr;
    const float* w[2] = {nullptr, nullptr};   // [msg_w, lin_w]
    const float* b[2] = {nullptr, nullptr};   // [msg_b, lin_b]
    int wi = 0, bi = 0;
    for (int i = 0; i < n_in; i++) {
        const int s = in_sizes[i];
        if      (s == N_NODES * DIM) X   = (const float*)d_in[i];
        else if (s == 2 * N_EDGES)   ei  = d_in[i];
        else if (s == 1)             eps = (const float*)d_in[i];
        else if (s == DIM * DIM)   { if (wi < 2) w[wi++] = (const float*)d_in[i]; }
        else if (s == DIM)         { if (bi < 2) b[bi++] = (const float*)d_in[i]; }
    }
    float* out = (float*)d_out;

    cudaFuncSetAttribute(final_kernel, cudaFuncAttributeMaxDynamicSharedMemorySize, SM_TOTAL);

    const int node_blocks = (N_NODES + 255) / 256;               // 196
    const int spmm_blocks = (N_NODES + 7) / 8;                   // 6250

    detect_zero_kernel<<<node_blocks, 256>>>((const unsigned*)ei);
    init_hist_kernel<<<INIT_BLOCKS + HIST_BLOCKS, 256>>>(w[1], X, eps, ei);
    prep_scan_kernel<<<17, 1024>>>(w[1], w[0], b[0]);
    reorder_kernel<<<HIST_BLOCKS, 256>>>(ei);
    spmm_kernel<<<spmm_blocks, 256>>>();
    final_kernel<<<NTILES, 256, SM_TOTAL>>>(b[1], out);
}

// round 17
// speedup vs baseline: 1.6586x; 1.6586x over previous
#include <cuda_runtime.h>
#include <cuda_fp16.h>
#include <cstdint>

#define DIM      128
#define N_NODES  50000
#define N_EDGES  625000
#define TILE_M   64
#define NTILES   ((N_NODES + TILE_M - 1) / TILE_M)   // 782

#define SCAN_BS  512
#define NBLK     ((N_NODES + SCAN_BS - 1) / SCAN_BS) // 98

#define INIT_BLOCKS  ((N_NODES * (DIM / 4) + 255) / 256)   // 6250
#define HIST_BLOCKS  ((N_EDGES / 4 + 255) / 256)           // 611

// SMEM geometry for final kernel: 64-row A tiles (hi only) + full 128-row B.
#define ASTRIDE   272
#define AB        (64 * ASTRIDE)                     // 17408
#define BB        (128 * ASTRIDE)                    // 34816
#define SM_A1H    0
#define SM_A2H    (AB)
#define SM_B1     (2 * AB)
#define SM_B2     (2 * AB + BB)
#define SM_TOTAL  (2 * AB + 2 * BB)                  // 104448 -> 2 CTAs/SM

// ---------------- scratch (device globals) ----------------------------------
__device__ __half g_aggH[(size_t)N_NODES * DIM];     // fp16 aggX
__device__ __half g_Xh[(size_t)N_NODES * DIM];       // fp16 copy of X
__device__ __half g_Wh[2][DIM * DIM];                // [(1+eps)lin_W, C=lin_W.msg_W]
__device__ float  g_c2[DIM];                         // lin_W . msg_b
__device__ int    g_ei_is_i64;
// CSR build
__device__ int    g_cnt[N_NODES];
__device__ int    g_off[N_NODES + 1];
__device__ int    g_cur[N_NODES];
__device__ int    g_bsum[NBLK];
__device__ int    g_sorted[N_EDGES];

// ---------------- helpers ----------------------------------------------------
__device__ __forceinline__ uint32_t smem_u32(const void* p) {
    uint32_t a;
    asm("{ .reg .u64 t; cvta.to.shared.u64 t, %1; cvt.u32.u64 %0, t; }" : "=r"(a) : "l"(p));
    return a;
}

#define LDSM_X4(r, addr)                                                        \
    asm volatile("ldmatrix.sync.aligned.m8n8.x4.shared.b16 {%0,%1,%2,%3}, [%4];"\
                 : "=r"((r)[0]), "=r"((r)[1]), "=r"((r)[2]), "=r"((r)[3])       \
                 : "r"(addr))
#define MMA_FP16(c, a, b0, b1)                                                  \
    asm volatile("mma.sync.aligned.m16n8k16.row.col.f32.f16.f16.f32 "           \
                 "{%0,%1,%2,%3}, {%4,%5,%6,%7}, {%8,%9}, {%0,%1,%2,%3};"        \
                 : "+f"((c)[0]), "+f"((c)[1]), "+f"((c)[2]), "+f"((c)[3])       \
                 : "r"((a)[0]), "r"((a)[1]), "r"((a)[2]), "r"((a)[3]),          \
                   "r"(b0), "r"(b1))

// vectorized 4-edge decode (src + dst)
__device__ __forceinline__ void edge_decode4(const void* ei, int e0,
                                             unsigned* s, unsigned* d) {
    if (g_ei_is_i64) {
        const longlong2* p = (const longlong2*)ei;
        longlong2 a = __ldg(p + e0 / 2), b = __ldg(p + e0 / 2 + 1);
        longlong2 c = __ldg(p + (N_EDGES + e0) / 2), e = __ldg(p + (N_EDGES + e0) / 2 + 1);
        s[0] = (unsigned)a.x; s[1] = (unsigned)a.y; s[2] = (unsigned)b.x; s[3] = (unsigned)b.y;
        d[0] = (unsigned)c.x; d[1] = (unsigned)c.y; d[2] = (unsigned)e.x; d[3] = (unsigned)e.y;
    } else {
        int4 a = __ldg((const int4*)ei + e0 / 4);
        int4 c = __ldg((const int4*)ei + (N_EDGES + e0) / 4);
        s[0] = (unsigned)a.x; s[1] = (unsigned)a.y; s[2] = (unsigned)a.z; s[3] = (unsigned)a.w;
        d[0] = (unsigned)c.x; d[1] = (unsigned)c.y; d[2] = (unsigned)c.z; d[3] = (unsigned)c.w;
    }
}

// 2-edge decode (for reorder: shorter serial atomic chains per thread)
__device__ __forceinline__ void edge_decode2(const void* ei, int e0,
                                             unsigned* s, unsigned* d) {
    if (g_ei_is_i64) {
        const longlong2* p = (const longlong2*)ei;
        longlong2 a = __ldg(p + e0 / 2);
        longlong2 c = __ldg(p + (N_EDGES + e0) / 2);
        s[0] = (unsigned)a.x; s[1] = (unsigned)a.y;
        d[0] = (unsigned)c.x; d[1] = (unsigned)c.y;
    } else {
        int2 a = __ldg((const int2*)ei + e0 / 2);
        int2 c = __ldg((const int2*)ei + (N_EDGES + e0) / 2);
        s[0] = (unsigned)a.x; s[1] = (unsigned)a.y;
        d[0] = (unsigned)c.x; d[1] = (unsigned)c.y;
    }
}

// ---------------- k1: detect dtype (block 0) + zero counters -----------------
__global__ void detect_zero_kernel(const unsigned* __restrict__ p32) {
    const int i = blockIdx.x * blockDim.x + threadIdx.x;
    if (i < N_NODES) g_cnt[i] = 0;
    if (blockIdx.x == 0) {
        __shared__ unsigned red[256];
        unsigned acc = 0;
        for (int k = threadIdx.x; k < 1024; k += 256) {
            acc |= p32[2 * k + 1];
            acc |= p32[2 * (N_EDGES / 2 + k) + 1];
        }
        red[threadIdx.x] = acc;
        __syncthreads();
        for (int s = 128; s > 0; s >>= 1) {
            if (threadIdx.x < s) red[threadIdx.x] |= red[threadIdx.x + s];
            __syncthreads();
        }
        if (threadIdx.x == 0) g_ei_is_i64 = (red[0] == 0) ? 1 : 0;
    }
}

// ---------------- k2: convert X/lin_W to fp16 (+hist, merged) ----------------
__global__ void init_hist_kernel(const float* __restrict__ lin_w,
                                 const float* __restrict__ X,
                                 const float* __restrict__ eps_ptr,
                                 const void* __restrict__ ei) {
    const int b = blockIdx.x;
    if (b < INIT_BLOCKS) {
        const int i = b * blockDim.x + threadIdx.x;
        if (i < DIM * DIM) {
            const float epsv = 1.0f + __ldg(eps_ptr);
            g_Wh[0][i] = __float2half(epsv * lin_w[i]);   // fold (1+eps) into B1
        }
        if (i < N_NODES * (DIM / 4)) {
            float4 v = __ldg((const float4*)X + i);
            __half2 h0 = __floats2half2_rn(v.x, v.y);
            __half2 h1 = __floats2half2_rn(v.z, v.w);
            uint2 u;
            u.x = *(uint32_t*)&h0;
            u.y = *(uint32_t*)&h1;
            ((uint2*)g_Xh)[i] = u;
        }
    } else {
        const int e0 = ((b - INIT_BLOCKS) * blockDim.x + threadIdx.x) * 4;
        if (e0 >= N_EDGES) return;
        unsigned s[4], d[4];
        edge_decode4(ei, e0, s, d);
        #pragma unroll
        for (int i = 0; i < 4; i++)
            if (e0 + i < N_EDGES && s[i] < N_NODES && d[i] < N_NODES)
                atomicAdd(&g_cnt[s[i]], 1);
    }
}

// C = lin_W . msg_W (fp32 acc, fp16 store); c2 = lin_W . msg_b
__global__ void prep_c_kernel(const float* __restrict__ lin_w,
                              const float* __restrict__ msg_w,
                              const float* __restrict__ msg_b) {
    __shared__ float s[DIM];
    __shared__ float red[DIM];
    const int i = blockIdx.x, j = threadIdx.x;
    s[j] = lin_w[(size_t)i * DIM + j];
    __syncthreads();
    float acc = 0.f;
    #pragma unroll 8
    for (int k = 0; k < DIM; k++)
        acc += s[k] * __ldg(msg_w + (size_t)k * DIM + j);
    g_Wh[1][(size_t)i * DIM + j] = __float2half(acc);
    red[j] = s[j] * __ldg(msg_b + j);
    __syncthreads();
    for (int st = 64; st > 0; st >>= 1) {
        if (j < st) red[j] += red[j + st];
        __syncthreads();
    }
    if (j == 0) g_c2[i] = red[0];
}

// ---------------- scans (proven round-15 versions) ----------------------------
__global__ void scanA_kernel() {
    __shared__ int sm[SCAN_BS];
    const int t = threadIdx.x, b = blockIdx.x;
    const int i = b * SCAN_BS + t;
    const int v = (i < N_NODES) ? g_cnt[i] : 0;
    sm[t] = v;
    __syncthreads();
    for (int off = 1; off < SCAN_BS; off <<= 1) {
        int x = (t >= off) ? sm[t - off] : 0;
        __syncthreads();
        sm[t] += x;
        __syncthreads();
    }
    if (i < N_NODES) g_off[i] = sm[t] - v;
    if (t == SCAN_BS - 1) g_bsum[b] = sm[t];
}

__global__ void scanB_kernel() {
    if (threadIdx.x == 0) {
        int acc = 0;
        for (int b = 0; b < NBLK; b++) {
            int v = g_bsum[b];
            g_bsum[b] = acc;
            acc += v;
        }
        g_off[N_NODES] = acc;
    }
}

__global__ void scanC_kernel() {
    const int i = blockIdx.x * blockDim.x + threadIdx.x;
    if (i >= N_NODES) return;
    const int o = g_off[i] + g_bsum[i / SCAN_BS];
    g_off[i] = o;
    g_cur[i] = o;
}

// reorder: 2 edges/thread (shorter serial atomic chains, 2x thread parallelism)
__global__ void reorder_kernel(const void* __restrict__ ei) {
    const int e0 = (blockIdx.x * blockDim.x + threadIdx.x) * 2;
    if (e0 >= N_EDGES) return;
    unsigned s[2], d[2];
    edge_decode2(ei, e0, s, d);
    #pragma unroll
    for (int i = 0; i < 2; i++)
        if (e0 + i < N_EDGES && s[i] < N_NODES && d[i] < N_NODES) {
            int pos = atomicAdd(&g_cur[s[i]], 1);
            g_sorted[pos] = (int)d[i];
        }
}

// ---------------- SpMM: aggH[n] = fp16( sum over CSR dst rows of fp16 X ) ----
__global__ void spmm_kernel() {
    const int node = blockIdx.x * (blockDim.x >> 5) + (threadIdx.x >> 5);
    if (node >= N_NODES) return;
    const int lane = threadIdx.x & 31;
    const int start = __ldg(&g_off[node]);
    const int end   = __ldg(&g_off[node + 1]);
    const uint2* Xh = (const uint2*)g_Xh;

    float4 a0 = make_float4(0.f, 0.f, 0.f, 0.f);
    float4 a1 = a0, a2 = a0, a3 = a0;
    int i = start;
    for (; i + 4 <= end; i += 4) {
        const int d0 = __ldg(&g_sorted[i + 0]);
        const int d1 = __ldg(&g_sorted[i + 1]);
        const int d2 = __ldg(&g_sorted[i + 2]);
        const int d3 = __ldg(&g_sorted[i + 3]);
        uint2 u0 = __ldg(Xh + (size_t)d0 * (DIM / 4) + lane);
        uint2 u1 = __ldg(Xh + (size_t)d1 * (DIM / 4) + lane);
        uint2 u2 = __ldg(Xh + (size_t)d2 * (DIM / 4) + lane);
        uint2 u3 = __ldg(Xh + (size_t)d3 * (DIM / 4) + lane);
        float2 p, q;
        p = __half22float2(*(__half2*)&u0.x); q = __half22float2(*(__half2*)&u0.y);
        a0.x += p.x; a0.y += p.y; a0.z += q.x; a0.w += q.y;
        p = __half22float2(*(__half2*)&u1.x); q = __half22float2(*(__half2*)&u1.y);
        a1.x += p.x; a1.y += p.y; a1.z += q.x; a1.w += q.y;
        p = __half22float2(*(__half2*)&u2.x); q = __half22float2(*(__half2*)&u2.y);
        a2.x += p.x; a2.y += p.y; a2.z += q.x; a2.w += q.y;
        p = __half22float2(*(__half2*)&u3.x); q = __half22float2(*(__half2*)&u3.y);
        a3.x += p.x; a3.y += p.y; a3.z += q.x; a3.w += q.y;
    }
    for (; i < end; i++) {
        const int d = __ldg(&g_sorted[i]);
        uint2 u = __ldg(Xh + (size_t)d * (DIM / 4) + lane);
        float2 p = __half22float2(*(__half2*)&u.x);
        float2 q = __half22float2(*(__half2*)&u.y);
        a0.x += p.x; a0.y += p.y; a0.z += q.x; a0.w += q.y;
    }
    a0.x += a1.x + a2.x + a3.x;
    a0.y += a1.y + a2.y + a3.y;
    a0.z += a1.z + a2.z + a3.z;
    a0.w += a1.w + a2.w + a3.w;
    __half2 h0 = __floats2half2_rn(a0.x, a0.y);
    __half2 h1 = __floats2half2_rn(a0.z, a0.w);
    uint2 u;
    u.x = *(uint32_t*)&h0;
    u.y = *(uint32_t*)&h1;
    ((uint2*)g_aggH)[(size_t)node * (DIM / 4) + lane] = u;
}

// ---------------- final: out = relu(Xh.[(1+eps)lin_W]^T + aggH.C^T + deg*c2 + lin_b)
// 64-row tiles, 256 threads (8 warps), 2 CTAs/SM. A1/A2 are pure fp16 copies.
__global__ void __launch_bounds__(256, 2)
final_kernel(const float* __restrict__ lin_b, float* __restrict__ out) {
    extern __shared__ char smem[];
    const uint32_t sb = smem_u32(smem);
    const int tid = threadIdx.x;
    const int w = tid >> 5, t = tid & 31;
    const int s = w >> 1, h = w & 1;
    const int g = t >> 2, tig = t & 3;
    const int base = blockIdx.x * TILE_M;

    // ---- fill: A1h = copy(Xh), A2h = copy(aggH), B1/B2 = copy ----
    {
        const int row = tid >> 2;                 // 0..63
        const int c0 = (tid & 3) * 32;
        const int grow = base + row;
        const bool v = (grow < N_NODES);
        uint4* a1d = (uint4*)(smem + SM_A1H + (uint32_t)row * ASTRIDE + (uint32_t)c0 * 2);
        uint4* a2d = (uint4*)(smem + SM_A2H + (uint32_t)row * ASTRIDE + (uint32_t)c0 * 2);
        if (v) {
            const uint4* a1s = (const uint4*)(g_Xh + (size_t)grow * DIM + c0);
            const uint4* a2s = (const uint4*)(g_aggH + (size_t)grow * DIM + c0);
            #pragma unroll
            for (int i = 0; i < 4; i++) { a1d[i] = __ldg(a1s + i); a2d[i] = __ldg(a2s + i); }
        } else {
            #pragma unroll
            for (int i = 0; i < 4; i++) {
                a1d[i] = make_uint4(0u, 0u, 0u, 0u);
                a2d[i] = make_uint4(0u, 0u, 0u, 0u);
            }
        }
        // B tiles: 128 rows; thread covers half a row (64 cols = 8 uint4)
        const int brow = tid >> 1;
        const int bc0 = (tid & 1) * 64;
        const uint4* b1s = (const uint4*)(&g_Wh[0][(size_t)brow * DIM + bc0]);
        const uint4* b2s = (const uint4*)(&g_Wh[1][(size_t)brow * DIM + bc0]);
        uint4* b1d = (uint4*)(smem + SM_B1 + (uint32_t)brow * ASTRIDE + (uint32_t)bc0 * 2);
        uint4* b2d = (uint4*)(smem + SM_B2 + (uint32_t)brow * ASTRIDE + (uint32_t)bc0 * 2);
        #pragma unroll
        for (int i = 0; i < 8; i++) { b1d[i] = __ldg(b1s + i); b2d[i] = __ldg(b2s + i); }
    }
    __syncthreads();

    float acc[8][4];
    #pragma unroll
    for (int j = 0; j < 8; j++)
        #pragma unroll
        for (int i = 0; i < 4; i++) acc[j][i] = 0.f;

    // ---- MMA: acc = A1h.B1 + A2h.B2 ----
    #pragma unroll 1
    for (int k = 0; k < 8; k++) {
        const uint32_t a_off = (uint32_t)(s * 16 + (t & 15)) * ASTRIDE
                             + (uint32_t)k * 32 + (uint32_t)(t >> 4) * 16;
        uint32_t a1[4], a2[4];
        LDSM_X4(a1, sb + SM_A1H + a_off);
        LDSM_X4(a2, sb + SM_A2H + a_off);
        #pragma unroll
        for (int jp = 0; jp < 4; jp++) {
            const uint32_t b_off =
                  (uint32_t)((h * 8 + jp * 2) * 8 + (t >> 4) * 8 + (t & 7)) * ASTRIDE
                + (uint32_t)k * 32 + (uint32_t)((t >> 3) & 1) * 16;
            uint32_t b1[4], b2[4];
            LDSM_X4(b1, sb + SM_B1 + b_off);
            LDSM_X4(b2, sb + SM_B2 + b_off);
            MMA_FP16(acc[jp * 2 + 0], a1, b1[0], b1[1]);
            MMA_FP16(acc[jp * 2 + 0], a2, b2[0], b2[1]);
            MMA_FP16(acc[jp * 2 + 1], a1, b1[2], b1[3]);
            MMA_FP16(acc[jp * 2 + 1], a2, b2[2], b2[3]);
        }
    }

    // ---- epilogue ----
    const int r0 = s * 16 + g, r1 = r0 + 8;
    const int gr0 = base + r0, gr1 = base + r1;
    const bool v0 = (gr0 < N_NODES), v1 = (gr1 < N_NODES);
    const float d0 = v0 ? (float)(__ldg(&g_off[gr0 + 1]) - __ldg(&g_off[gr0])) : 0.f;
    const float d1 = v1 ? (float)(__ldg(&g_off[gr1 + 1]) - __ldg(&g_off[gr1])) : 0.f;
    #pragma unroll
    for (int j = 0; j < 8; j++) {
        const int col = h * 64 + j * 8 + 2 * tig;
        float2 lb = __ldg((const float2*)(lin_b + col));
        float2 c2 = __ldg((const float2*)(g_c2 + col));
        if (v0) {
            float2 o;
            o.x = fmaxf(acc[j][0] + d0 * c2.x + lb.x, 0.f);
            o.y = fmaxf(acc[j][1] + d0 * c2.y + lb.y, 0.f);
            *(float2*)(out + (size_t)gr0 * DIM + col) = o;
        }
        if (v1) {
            float2 o;
            o.x = fmaxf(acc[j][2] + d1 * c2.x + lb.x, 0.f);
            o.y = fmaxf(acc[j][3] + d1 * c2.y + lb.y, 0.f);
            *(float2*)(out + (size_t)gr1 * DIM + col) = o;
        }
    }
}

// ---------------- launch ----------------------------------------------------
extern "C" void kernel_launch(void* const* d_in, const int* in_sizes, int n_in,
                              void* d_out, int out_size) {
    const float* X   = nullptr;
    const void*  ei  = nullptr;
    const float* eps = nullptr;
    const float* w[2] = {nullptr, nullptr};   // [msg_w, lin_w]
    const float* b[2] = {nullptr, nullptr};   // [msg_b, lin_b]
    int wi = 0, bi = 0;
    for (int i = 0; i < n_in; i++) {
        const int s = in_sizes[i];
        if      (s == N_NODES * DIM) X   = (const float*)d_in[i];
        else if (s == 2 * N_EDGES)   ei  = d_in[i];
        else if (s == 1)             eps = (const float*)d_in[i];
        else if (s == DIM * DIM)   { if (wi < 2) w[wi++] = (const float*)d_in[i]; }
        else if (s == DIM)         { if (bi < 2) b[bi++] = (const float*)d_in[i]; }
    }
    float* out = (float*)d_out;

    cudaFuncSetAttribute(final_kernel, cudaFuncAttributeMaxDynamicSharedMemorySize, SM_TOTAL);

    const int node_blocks = (N_NODES + 255) / 256;               // 196
    const int edge2_blocks = (N_EDGES / 2 + 255) / 256;          // 1221
    const int spmm_blocks = (N_NODES + 7) / 8;                   // 6250

    detect_zero_kernel<<<node_blocks, 256>>>((const unsigned*)ei);
    init_hist_kernel<<<INIT_BLOCKS + HIST_BLOCKS, 256>>>(w[1], X, eps, ei);
    prep_c_kernel<<<DIM, DIM>>>(w[1], w[0], b[0]);
    scanA_kernel<<<NBLK, SCAN_BS>>>();
    scanB_kernel<<<1, 32>>>();
    scanC_kernel<<<node_blocks, 256>>>();
    reorder_kernel<<<edge2_blocks, 256>>>(ei);
    spmm_kernel<<<spmm_blocks, 256>>>();
    final_kernel<<<NTILES, 256, SM_TOTAL>>>(b[1], out);
}